// round 1
// baseline (speedup 1.0000x reference)
#include <cuda_runtime.h>

#define T_STEPS 128
#define H       20
#define H3      60
#define NB      2048
#define LOUT    15
#define EPB     8        // batch elements per block
#define THREADS 32       // 4 threads per element

typedef unsigned long long u64;

__device__ __forceinline__ u64 dup2(float a) {
    u64 r; asm("mov.b64 %0,{%1,%1};" : "=l"(r) : "f"(a)); return r;
}
__device__ __forceinline__ u64 ffma2(u64 a, u64 b, u64 c) {
    u64 d; asm("fma.rn.f32x2 %0,%1,%2,%3;" : "=l"(d) : "l"(a), "l"(b), "l"(c)); return d;
}
__device__ __forceinline__ void unp(u64 p, float& lo, float& hi) {
    asm("mov.b64 {%0,%1},%2;" : "=f"(lo), "=f"(hi) : "l"(p));
}
__device__ __forceinline__ float sigm(float x) {
    float e = __expf(-x);
    return __fdividef(1.f, 1.f + e);
}
__device__ __forceinline__ float tanh_f(float x) {
    x = fminf(fmaxf(x, -30.f), 30.f);
    float e = __expf(-2.f * x);
    return __fdividef(1.f - e, 1.f + e);
}
__device__ __forceinline__ void toF5(u64 A, u64 B, float C, float o[5]) {
    unp(A, o[0], o[1]); unp(B, o[2], o[3]); o[4] = C;
}

// rec/xw matvec over 21 "rows" (row 20 = bias, h[20]=1). Thread owns, per gate,
// cols {r4..r4+3, r16}. M is SMEM [21][60], hb is SMEM [21].
__device__ __forceinline__ void matvec(const float* __restrict__ M,
                                       const float* __restrict__ hb,
                                       int r4, int r16,
                                       u64 A[3], u64 Bv[3], float C[3]) {
#pragma unroll
    for (int g = 0; g < 3; g++) { A[g] = 0ull; Bv[g] = 0ull; C[g] = 0.f; }
#pragma unroll
    for (int k = 0; k < 21; k++) {
        float hk = hb[k];
        u64 h2 = dup2(hk);
#pragma unroll
        for (int g = 0; g < 3; g++) {
            const float* base = M + k * H3 + g * H;
            ulonglong2 q = *reinterpret_cast<const ulonglong2*>(base + r4);  // 16B aligned
            A[g]  = ffma2(h2, q.x, A[g]);
            Bv[g] = ffma2(h2, q.y, Bv[g]);
            C[g]  = fmaf(hk, base[r16], C[g]);
        }
    }
}

__device__ __forceinline__ void gru_update(const float xz[5], const float xr[5], const float xh[5],
                                           const float rz[5], const float rr[5], const float rh[5],
                                           float ho[5]) {
#pragma unroll
    for (int j = 0; j < 5; j++) {
        float z  = sigm(xz[j] + rz[j]);
        float rg = sigm(xr[j] + rr[j]);
        float hh = tanh_f(xh[j] + rg * rh[j]);
        ho[j] = z * (ho[j] - hh) + hh;   // z*h + (1-z)*hh
    }
}

__global__ void __launch_bounds__(THREADS)
gru2_kernel(const int* __restrict__ x,
            const float* __restrict__ W0,
            const float* __restrict__ U0, const float* __restrict__ b0i, const float* __restrict__ b0r,
            const float* __restrict__ W1, const float* __restrict__ U1,
            const float* __restrict__ b1i, const float* __restrict__ b1r,
            const float* __restrict__ Wd, const float* __restrict__ bd,
            float* __restrict__ out)
{
    __shared__ __align__(16) float U0x[21 * H3];   // rows 0-19: U0, row 20: b0r (+b0i for z,r cols)
    __shared__ __align__(16) float W1x[21 * H3];   // rows 0-19: W1, row 20: b1i
    __shared__ __align__(16) float U1x[21 * H3];   // rows 0-19: U1, row 20: b1r
    __shared__ float Wdx[21 * LOUT];               // rows 0-19: Wd, row 20: bd
    __shared__ int   xs[EPB * T_STEPS];
    __shared__ float hs0[2][EPB][21];              // double-buffered h state, [.][e][20]=1
    __shared__ float hs1[2][EPB][21];

    const int tid = threadIdx.x;

    for (int i = tid; i < 21 * H3; i += THREADS) {
        int row = i / H3, c = i - row * H3;
        U0x[i] = (row < H) ? U0[i] : (b0r[c] + (c < 2 * H ? b0i[c] : 0.f));
        W1x[i] = (row < H) ? W1[i] : b1i[c];
        U1x[i] = (row < H) ? U1[i] : b1r[c];
    }
    for (int i = tid; i < 21 * LOUT; i += THREADS)
        Wdx[i] = (i < H * LOUT) ? Wd[i] : bd[i - H * LOUT];
    for (int i = tid; i < EPB * T_STEPS; i += THREADS)
        xs[i] = x[blockIdx.x * EPB * T_STEPS + i];
    for (int i = tid; i < 2 * EPB * 21; i += THREADS) {
        float v = ((i % 21) == 20) ? 1.f : 0.f;
        (&hs0[0][0][0])[i] = v;
        (&hs1[0][0][0])[i] = v;
    }
    __syncthreads();

    const int e = tid >> 2, r = tid & 3;
    const int r4 = 4 * r, r16 = 16 + r;

    // b0i for the h-gate stays separate (hh = tanh(xh + b0i_h + r*rh), NOT summed with b0r)
    float b0h[5];
#pragma unroll
    for (int j = 0; j < 4; j++) b0h[j] = b0i[2 * H + r4 + j];
    b0h[4] = b0i[2 * H + r16];

    float h0own[5] = {0, 0, 0, 0, 0};
    float h1own[5] = {0, 0, 0, 0, 0};
    const int* xrow = &xs[e * T_STEPS];

    for (int t = 0; t < T_STEPS; t++) {
        const int cur = t & 1, nxt = cur ^ 1;

        // xw0 = W0[x_t] row (b0i for z,r gates folded into U0x bias row; h-gate via b0h)
        const float* w0row = W0 + xrow[t] * H3;
        float xz[5], xrg[5], xh[5];
        {
            float4 q0 = *reinterpret_cast<const float4*>(w0row + 0 * H + r4);
            float4 q1 = *reinterpret_cast<const float4*>(w0row + 1 * H + r4);
            float4 q2 = *reinterpret_cast<const float4*>(w0row + 2 * H + r4);
            xz[0] = q0.x; xz[1] = q0.y; xz[2] = q0.z; xz[3] = q0.w; xz[4] = w0row[0 * H + r16];
            xrg[0] = q1.x; xrg[1] = q1.y; xrg[2] = q1.z; xrg[3] = q1.w; xrg[4] = w0row[1 * H + r16];
            xh[0] = q2.x; xh[1] = q2.y; xh[2] = q2.z; xh[3] = q2.w; xh[4] = w0row[2 * H + r16];
        }
#pragma unroll
        for (int j = 0; j < 5; j++) xh[j] += b0h[j];

        // rec0 = h0 @ U0 (+biases via row 20)
        u64 A0[3], B0[3]; float C0[3];
        matvec(U0x, hs0[cur][e], r4, r16, A0, B0, C0);
        float rz[5], rr[5], rh[5];
        toF5(A0[0], B0[0], C0[0], rz);
        toF5(A0[1], B0[1], C0[1], rr);
        toF5(A0[2], B0[2], C0[2], rh);
        gru_update(xz, xrg, xh, rz, rr, rh, h0own);

        // rec1 = h1_old @ U1 — independent of h0 publish, do it before the sync
        u64 A1[3], B1[3]; float C1[3];
        matvec(U1x, hs1[cur][e], r4, r16, A1, B1, C1);

        // publish h0_new
#pragma unroll
        for (int j = 0; j < 4; j++) hs0[nxt][e][r4 + j] = h0own[j];
        hs0[nxt][e][r16] = h0own[4];
        __syncwarp();

        // xw1 = h0_new @ W1 (+b1i via row 20)
        u64 A2[3], B2[3]; float C2[3];
        matvec(W1x, hs0[nxt][e], r4, r16, A2, B2, C2);

        float xz1[5], xr1[5], xh1[5], rz1[5], rr1[5], rh1[5];
        toF5(A2[0], B2[0], C2[0], xz1);
        toF5(A2[1], B2[1], C2[1], xr1);
        toF5(A2[2], B2[2], C2[2], xh1);
        toF5(A1[0], B1[0], C1[0], rz1);
        toF5(A1[1], B1[1], C1[1], rr1);
        toF5(A1[2], B1[2], C1[2], rh1);
        gru_update(xz1, xr1, xh1, rz1, rr1, rh1, h1own);

        // publish h1_new
#pragma unroll
        for (int j = 0; j < 4; j++) hs1[nxt][e][r4 + j] = h1own[j];
        hs1[nxt][e][r16] = h1own[4];
        __syncwarp();
    }

    // logits = softmax(h1 @ Wd + bd); every thread of the element computes all 15 (cheap, once)
    const float* h1f = hs1[T_STEPS & 1][e];
    float lg[LOUT];
#pragma unroll
    for (int c = 0; c < LOUT; c++) lg[c] = 0.f;
#pragma unroll
    for (int k = 0; k < 21; k++) {
        float hk = h1f[k];
#pragma unroll
        for (int c = 0; c < LOUT; c++) lg[c] = fmaf(hk, Wdx[k * LOUT + c], lg[c]);
    }
    float m = lg[0];
#pragma unroll
    for (int c = 1; c < LOUT; c++) m = fmaxf(m, lg[c]);
    float p[LOUT], s = 0.f;
#pragma unroll
    for (int c = 0; c < LOUT; c++) { p[c] = __expf(lg[c] - m); s += p[c]; }
    float inv = __fdividef(1.f, s);

    const int b = blockIdx.x * EPB + e;
    for (int c = r; c < LOUT; c += 4)
        out[b * LOUT + c] = p[c] * inv;
}

extern "C" void kernel_launch(void* const* d_in, const int* in_sizes, int n_in,
                              void* d_out, int out_size) {
    const int*   x   = (const int*)d_in[0];
    const float* W0  = (const float*)d_in[1];
    const float* U0  = (const float*)d_in[2];
    const float* b0i = (const float*)d_in[3];
    const float* b0r = (const float*)d_in[4];
    const float* W1  = (const float*)d_in[5];
    const float* U1  = (const float*)d_in[6];
    const float* b1i = (const float*)d_in[7];
    const float* b1r = (const float*)d_in[8];
    const float* Wd  = (const float*)d_in[9];
    const float* bd  = (const float*)d_in[10];
    // d_in[11] = drop_rate (identity dropout), unused

    gru2_kernel<<<NB / EPB, THREADS>>>(x, W0, U0, b0i, b0r, W1, U1, b1i, b1r, Wd, bd,
                                       (float*)d_out);
}